// round 2
// baseline (speedup 1.0000x reference)
#include <cuda_runtime.h>

// ---------------------------------------------------------------------------
// RticCompositionModule — collapsed computation.
// Key identity: BN over the batch axis of a row broadcast to all 32 batch
// rows yields exactly the BN bias (mean==value exactly, var==0). So every
// vmap slice over text_features is identical: compute ONE [32,4096] compose
// and broadcast it 32x into the [32,32,4096] output.
// ---------------------------------------------------------------------------

#define E_DIM 4096
#define H_DIM 2048
#define MROWS 32
#define BK 32

typedef unsigned long long ull;

// ---- scratch (device globals; no allocation allowed) ----
__device__ float g_xi[MROWS * E_DIM];        // relu(BN(image))
__device__ float g_xt[E_DIM];                // relu(fs_bn_b[E:2E])  (text-half BN output)
__device__ float g_part[16 * MROWS * E_DIM]; // split-K partials (8 MB, max over stages)
__device__ float g_partv[16 * E_DIM];        // GEMV partials
__device__ float g_f[MROWS * E_DIM];         // fusion output f
__device__ float g_r1[MROWS * E_DIM];        // relu(BN(gating hidden))
__device__ float g_gate[MROWS * E_DIM];      // sigmoid gate g
__device__ float g_h[MROWS * H_DIM];         // ee hidden
__device__ float g_ff[MROWS * E_DIM];        // ee running residual

// ---- packed fp32x2 helpers (sm_103a: only path to full fp32 FMA rate) ----
__device__ __forceinline__ ull dup2(float v) {
    ull r; asm("mov.b64 %0, {%1, %1};" : "=l"(r) : "f"(v)); return r;
}
__device__ __forceinline__ void fma2(ull& d, ull a, ull b) {
    asm("fma.rn.f32x2 %0, %1, %2, %0;" : "+l"(d) : "l"(a), "l"(b));
}
__device__ __forceinline__ float2 u2f(ull v) {
    float2 f; asm("mov.b64 {%0, %1}, %2;" : "=f"(f.x), "=f"(f.y) : "l"(v)); return f;
}

// ---------------------------------------------------------------------------
// pre: BN(image) stats per column over 32 rows -> xi = relu(bn(image));
//      xt = relu(fs_bn_b[E:2E])   (exact text-half BN output)
// ---------------------------------------------------------------------------
__global__ void pre_kernel(const float* __restrict__ img,
                           const float* __restrict__ bng,
                           const float* __restrict__ bnb) {
    int c = blockIdx.x * blockDim.x + threadIdx.x;
    if (c >= E_DIM) return;
    float v[MROWS];
    float s = 0.f;
#pragma unroll
    for (int m = 0; m < MROWS; ++m) { v[m] = img[m * E_DIM + c]; s += v[m]; }
    float mu = s * (1.f / 32.f);
    float s2 = 0.f;
#pragma unroll
    for (int m = 0; m < MROWS; ++m) { float d = v[m] - mu; s2 += d * d; }
    float rs = rsqrtf(s2 * (1.f / 32.f) + 1e-5f);
    float gg = bng[c], bb = bnb[c];
#pragma unroll
    for (int m = 0; m < MROWS; ++m) {
        float o = (v[m] - mu) * rs * gg + bb;
        g_xi[m * E_DIM + c] = fmaxf(o, 0.f);
    }
    g_xt[c] = fmaxf(bnb[E_DIM + c], 0.f);
}

// ---------------------------------------------------------------------------
// Split-K GEMM: part[ks][32][N] = A[32][k0:k0+kslice] @ W[k0:k0+kslice][N]
// block = 128 threads: rg = warp (4 row-groups of 8 rows), cg = lane (32
// column-groups of 8 cols) -> block tile 32 x 256. Thread microtile 8x8,
// accumulators are 32 packed f32x2. Inner loop per k:
//   2x LDG.128 (W), 8x LDS.64 (A dup-pair broadcast), 32x FFMA2.
// aSel picks the activation buffer (all device globals).
// ---------------------------------------------------------------------------
__global__ void __launch_bounds__(128)
gemm_kernel(int aSel, const float* __restrict__ W, int K, int N, int kslice) {
    const float* A = (aSel == 0) ? g_xi
                   : (aSel == 1) ? g_f
                   : (aSel == 2) ? g_r1
                   : (aSel == 3) ? g_h
                                 : g_ff;
    __shared__ ull sA[BK][MROWS + 1];
    const int cg = threadIdx.x & 31;
    const int rg = threadIdx.x >> 5;
    const int n0 = blockIdx.x * 256 + cg * 8;
    const int k0 = blockIdx.y * kslice;

    ull acc[8][4];
#pragma unroll
    for (int r = 0; r < 8; ++r)
#pragma unroll
        for (int p = 0; p < 4; ++p) acc[r][p] = 0ull;

    for (int kb = k0; kb < k0 + kslice; kb += BK) {
        __syncthreads();
#pragma unroll
        for (int i = threadIdx.x; i < MROWS * BK; i += 128) {
            int kk = i & (BK - 1);
            int m  = i >> 5;
            sA[kk][m] = dup2(A[(size_t)m * K + kb + kk]);
        }
        __syncthreads();
#pragma unroll 4
        for (int kk = 0; kk < BK; ++kk) {
            const float* wp = W + (size_t)(kb + kk) * N + n0;
            ulonglong2 wa = *reinterpret_cast<const ulonglong2*>(wp);
            ulonglong2 wb = *reinterpret_cast<const ulonglong2*>(wp + 4);
#pragma unroll
            for (int r = 0; r < 8; ++r) {
                ull a = sA[kk][rg * 8 + r];
                fma2(acc[r][0], a, wa.x);
                fma2(acc[r][1], a, wa.y);
                fma2(acc[r][2], a, wb.x);
                fma2(acc[r][3], a, wb.y);
            }
        }
    }
    size_t base = (size_t)blockIdx.y * MROWS * N;
#pragma unroll
    for (int r = 0; r < 8; ++r) {
        int m = rg * 8 + r;
        float2 v0 = u2f(acc[r][0]), v1 = u2f(acc[r][1]);
        float2 v2 = u2f(acc[r][2]), v3 = u2f(acc[r][3]);
        float4* o = reinterpret_cast<float4*>(&g_part[base + (size_t)m * N + n0]);
        o[0] = make_float4(v0.x, v0.y, v1.x, v1.y);
        o[1] = make_float4(v2.x, v2.y, v3.x, v3.y);
    }
    (void)W; // part buffer is the fixed global
}

// ---------------------------------------------------------------------------
// GEMV for the constant text contribution: partv[ks][n] = sum_k xt[k]*Wbot[k][n]
// ---------------------------------------------------------------------------
__global__ void gemv_kernel(const float* __restrict__ W, int kslice) {
    int n  = blockIdx.x * blockDim.x + threadIdx.x;   // N = 4096
    int k0 = blockIdx.y * kslice;
    float acc = 0.f;
#pragma unroll 8
    for (int k = 0; k < kslice; ++k)
        acc += __ldg(&g_xt[k0 + k]) * W[(size_t)(k0 + k) * E_DIM + n];
    g_partv[(size_t)blockIdx.y * E_DIM + n] = acc;
}

// ---------------------------------------------------------------------------
// Epilogues
// ---------------------------------------------------------------------------
// fusion: f = sum_s part + sum_s partv + fs_b
__global__ void epi_fusion(const float* __restrict__ bias, int ksp) {
    int idx = blockIdx.x * blockDim.x + threadIdx.x;   // 32*4096
    int n = idx & (E_DIM - 1);
    float v = bias[n];
    for (int s = 0; s < ksp; ++s) v += g_part[(size_t)s * MROWS * E_DIM + idx];
    for (int s = 0; s < 16; ++s)  v += g_partv[(size_t)s * E_DIM + n];
    g_f[idx] = v;
}

// BN+ReLU epilogue: one warp per column (lane = batch row). outSel 0->g_r1, 1->g_h
__global__ void epi_bn_relu(const float* __restrict__ bias,
                            const float* __restrict__ gam,
                            const float* __restrict__ bet,
                            int N, int ksp, int outSel) {
    int m = threadIdx.x & 31;
    int c = blockIdx.x * 8 + (threadIdx.x >> 5);
    float v = bias[c];
    for (int s = 0; s < ksp; ++s)
        v += g_part[(size_t)s * MROWS * N + (size_t)m * N + c];
    float sum = v;
#pragma unroll
    for (int o = 16; o; o >>= 1) sum += __shfl_xor_sync(0xffffffffu, sum, o);
    float mu = sum * (1.f / 32.f);
    float d = v - mu;
    float s2 = d * d;
#pragma unroll
    for (int o = 16; o; o >>= 1) s2 += __shfl_xor_sync(0xffffffffu, s2, o);
    float rs = rsqrtf(s2 * (1.f / 32.f) + 1e-5f);
    float outv = fmaxf(d * rs * gam[c] + bet[c], 0.f);
    float* out = outSel ? g_h : g_r1;
    out[(size_t)m * N + c] = outv;
}

__global__ void epi_sigmoid(const float* __restrict__ bias, int ksp) {
    int idx = blockIdx.x * blockDim.x + threadIdx.x;   // 32*4096
    int n = idx & (E_DIM - 1);
    float v = bias[n];
    for (int s = 0; s < ksp; ++s) v += g_part[(size_t)s * MROWS * E_DIM + idx];
    g_gate[idx] = 1.f / (1.f + expf(-v));
}

// residual epilogue: g_ff = sum_s part + bias + resid (resid: 0 -> g_f, 1 -> g_ff)
__global__ void epi_res(const float* __restrict__ bias, int ksp, int residSel) {
    int idx = blockIdx.x * blockDim.x + threadIdx.x;   // 32*4096
    int n = idx & (E_DIM - 1);
    const float* resid = residSel ? g_ff : g_f;
    float v = bias[n] + resid[idx];
    for (int s = 0; s < ksp; ++s) v += g_part[(size_t)s * MROWS * E_DIM + idx];
    g_ff[idx] = v;
}

// final: R = img*g + ff*(1-g); broadcast 32x along the text axis
__global__ void final_kernel(const float* __restrict__ img, float* __restrict__ out) {
    int idx = blockIdx.x * blockDim.x + threadIdx.x;   // 32*4096
    float gv = g_gate[idx];
    float r = img[idx] * gv + g_ff[idx] * (1.f - gv);
#pragma unroll
    for (int j = 0; j < 32; ++j)
        out[(size_t)j * (MROWS * E_DIM) + idx] = r;
}

// ---------------------------------------------------------------------------
extern "C" void kernel_launch(void* const* d_in, const int* in_sizes, int n_in,
                              void* d_out, int out_size) {
    const float* img     = (const float*)d_in[0];
    // d_in[1] = text_features: provably unused (BN of a broadcast row == bias)
    const float* fs_bn_g = (const float*)d_in[2];
    const float* fs_bn_b = (const float*)d_in[3];
    const float* fs_w    = (const float*)d_in[4];
    const float* fs_b    = (const float*)d_in[5];
    const float* gt_w1   = (const float*)d_in[6];
    const float* gt_b1   = (const float*)d_in[7];
    const float* gt_bn_g = (const float*)d_in[8];
    const float* gt_bn_b = (const float*)d_in[9];
    const float* gt_w2   = (const float*)d_in[10];
    const float* gt_b2   = (const float*)d_in[11];
    const float* ee_w1   = (const float*)d_in[12];
    const float* ee_b1   = (const float*)d_in[13];
    const float* ee_bn_g = (const float*)d_in[14];
    const float* ee_bn_b = (const float*)d_in[15];
    const float* ee_w2   = (const float*)d_in[16];
    const float* ee_b2   = (const float*)d_in[17];
    float* out = (float*)d_out;

    // 0) image BN + relu, constant text vector
    pre_kernel<<<16, 256>>>(img, fs_bn_g, fs_bn_b);

    // 1) fusion: f = xi @ fs_w[0:E] + xt @ fs_w[E:2E] + fs_b
    gemm_kernel<<<dim3(16, 16), 128>>>(0, fs_w, E_DIM, E_DIM, 256);
    gemv_kernel<<<dim3(16, 16), 256>>>(fs_w + (size_t)E_DIM * E_DIM, 256);
    epi_fusion<<<512, 256>>>(fs_b, 16);

    // 2) gating
    gemm_kernel<<<dim3(16, 16), 128>>>(1, gt_w1, E_DIM, E_DIM, 256);
    epi_bn_relu<<<512, 256>>>(gt_b1, gt_bn_g, gt_bn_b, E_DIM, 16, 0);
    gemm_kernel<<<dim3(16, 16), 128>>>(2, gt_w2, E_DIM, E_DIM, 256);
    epi_sigmoid<<<512, 256>>>(gt_b2, 16);

    // 3) three error-encoding residual blocks
    for (int i = 0; i < 3; ++i) {
        int aSel = (i == 0) ? 1 : 4;  // first block reads f, then ff
        gemm_kernel<<<dim3(8, 32), 128>>>(aSel, ee_w1 + (size_t)i * E_DIM * H_DIM,
                                          E_DIM, H_DIM, 128);
        epi_bn_relu<<<256, 256>>>(ee_b1 + i * H_DIM, ee_bn_g + i * H_DIM,
                                  ee_bn_b + i * H_DIM, H_DIM, 32, 1);
        gemm_kernel<<<dim3(16, 16), 128>>>(3, ee_w2 + (size_t)i * H_DIM * E_DIM,
                                           H_DIM, E_DIM, 128);
        epi_res<<<512, 256>>>(ee_b2 + i * E_DIM, 16, (i == 0) ? 0 : 1);
    }

    // 4) gate-combine and broadcast to [32, 32, 4096]
    final_kernel<<<512, 256>>>(img, out);

    (void)in_sizes; (void)n_in; (void)out_size;
}

// round 3
// speedup vs baseline: 1.6504x; 1.6504x over previous
#include <cuda_runtime.h>

// ---------------------------------------------------------------------------
// RticCompositionModule — collapsed computation.
// BN over the batch axis of a broadcast row == BN bias exactly, so all 32
// vmap slices are identical: compute ONE [32,4096] compose, broadcast x32.
//
// GEMM design (this round): thread = 32 rows x 2 cols, packed fp32x2 FMAs,
// W streamed with __ldcs + depth-4 register prefetch, split-K partials kept
// L2-resident, coalesced fused reduction epilogues.
// ---------------------------------------------------------------------------

#define E_DIM 4096
#define H_DIM 2048
#define MROWS 32
#define BK 32

typedef unsigned long long ull;

// ---- scratch (device globals; no allocation allowed) ----
__device__ float g_xi[MROWS * E_DIM];     // relu(BN(image))
__device__ float g_xt[E_DIM];             // relu(fs_bn_b[E:2E]) (text-half BN out)
__device__ float g_part[4194304];         // split-K partials (16 MB, max layout)
__device__ float g_partv[32 * E_DIM];     // GEMV partials
__device__ float g_tvec[E_DIM];           // reduced text contribution
__device__ float g_f[MROWS * E_DIM];      // fusion output f
__device__ float g_r1[MROWS * E_DIM];     // relu(BN(gating hidden))
__device__ float g_gate[MROWS * E_DIM];   // sigmoid gate
__device__ float g_h[MROWS * H_DIM];      // ee hidden
__device__ float g_ff[MROWS * E_DIM];     // ee running residual

// ---- packed fp32x2 helpers ----
__device__ __forceinline__ ull dup2(float v) {
    ull r; asm("mov.b64 %0, {%1, %1};" : "=l"(r) : "f"(v)); return r;
}
__device__ __forceinline__ void fma2(ull& d, ull a, ull b) {
    asm("fma.rn.f32x2 %0, %1, %2, %0;" : "+l"(d) : "l"(a), "l"(b));
}
__device__ __forceinline__ ull ldcs64(const float* p) {
    ull v; asm("ld.global.cs.b64 %0, [%1];" : "=l"(v) : "l"(p)); return v;
}

// activation selectors
#define SEL_XI 0
#define SEL_F  1
#define SEL_R1 2
#define SEL_H  3
#define SEL_FF 4

// ---------------------------------------------------------------------------
// pre: xi = relu(BN(image)) ; xt = relu(fs_bn_b[E:2E])
// ---------------------------------------------------------------------------
__global__ void pre_kernel(const float* __restrict__ img,
                           const float* __restrict__ bng,
                           const float* __restrict__ bnb) {
    int c = blockIdx.x * blockDim.x + threadIdx.x;
    float v[MROWS];
    float s = 0.f;
#pragma unroll
    for (int m = 0; m < MROWS; ++m) { v[m] = img[m * E_DIM + c]; s += v[m]; }
    float mu = s * (1.f / 32.f);
    float s2 = 0.f;
#pragma unroll
    for (int m = 0; m < MROWS; ++m) { float d = v[m] - mu; s2 += d * d; }
    float rs = rsqrtf(s2 * (1.f / 32.f) + 1e-5f);
    float gg = bng[c], bb = bnb[c];
#pragma unroll
    for (int m = 0; m < MROWS; ++m)
        g_xi[m * E_DIM + c] = fmaxf((v[m] - mu) * rs * gg + bb, 0.f);
    g_xt[c] = fmaxf(bnb[E_DIM + c], 0.f);
}

// ---------------------------------------------------------------------------
// GEMM: part[ks][32][N] += A[32][k0:k0+kslice] @ W[k0:k0+kslice][N]
// 128 threads; thread owns ALL 32 rows x 2 cols (block tile 32 x 256).
// acc = 32 packed f32x2. Per k: 1 LDG.64 (distinct W per thread, __ldcs,
// prefetched 4 deep), 16 LDS.128 (A dup-pairs broadcast), 32 FFMA2.
// ---------------------------------------------------------------------------
__global__ void __launch_bounds__(128, 4)
gemm_kernel(int aSel, const float* __restrict__ W, int K, int N, int kslice) {
    const float* A = (aSel == SEL_XI) ? g_xi
                   : (aSel == SEL_F)  ? g_f
                   : (aSel == SEL_R1) ? g_r1
                   : (aSel == SEL_H)  ? g_h
                                      : g_ff;
    __shared__ __align__(16) ull sA[BK][MROWS];   // [kk][row], dup-pairs
    const int tid = threadIdx.x;
    const int col = blockIdx.x * 256 + tid * 2;
    const int k0  = blockIdx.y * kslice;

    ull acc[MROWS];
#pragma unroll
    for (int m = 0; m < MROWS; ++m) acc[m] = 0ull;

    const float* wp = W + (size_t)k0 * N + col;

    // prefetch ring, distance 4
    ull wreg[4];
#pragma unroll
    for (int p = 0; p < 4; ++p) wreg[p] = ldcs64(wp + (size_t)p * N);
    const float* wpf = wp + (size_t)4 * N;

    for (int kb = 0; kb < kslice; kb += BK) {
        __syncthreads();
        // stage A tile: lane = row (coalesce via L1/L2-hot activations)
#pragma unroll
        for (int it = 0; it < (MROWS * BK) / 128; ++it) {
            int m  = tid & 31;
            int kk = (tid >> 5) + it * 4;
            sA[kk][m] = dup2(A[(size_t)m * K + k0 + kb + kk]);
        }
        __syncthreads();
#pragma unroll 4
        for (int kk = 0; kk < BK; ++kk) {
            int k = kb + kk;
            ull w = wreg[k & 3];
            if (k + 4 < kslice) wreg[k & 3] = ldcs64(wpf);
            wpf += N;
#pragma unroll
            for (int j = 0; j < 16; ++j) {
                ulonglong2 a2 = *reinterpret_cast<const ulonglong2*>(&sA[kk][2 * j]);
                fma2(acc[2 * j],     a2.x, w);
                fma2(acc[2 * j + 1], a2.y, w);
            }
        }
    }
    // store partials (bit-identical packed floats)
    ull* base = reinterpret_cast<ull*>(g_part + (size_t)blockIdx.y * MROWS * N + col);
#pragma unroll
    for (int m = 0; m < MROWS; ++m)
        base[(size_t)m * (N / 2)] = acc[m];
}

// ---------------------------------------------------------------------------
// GEMV for constant text contribution: partv[ks][n] = sum_k xt[k]*Wbot[k][n]
// ---------------------------------------------------------------------------
__global__ void gemv_kernel(const float* __restrict__ W, int kslice) {
    int n  = blockIdx.x * 256 + threadIdx.x;
    int k0 = blockIdx.y * kslice;
    float acc = 0.f;
#pragma unroll 8
    for (int k = 0; k < kslice; ++k)
        acc += g_xt[k0 + k] * __ldcs(&W[(size_t)(k0 + k) * E_DIM + n]);
    g_partv[blockIdx.y * E_DIM + n] = acc;
}

__global__ void reduce_tvec(void) {
    int c = blockIdx.x * 256 + threadIdx.x;
    float s = 0.f;
#pragma unroll
    for (int sl = 0; sl < 32; ++sl) s += g_partv[sl * E_DIM + c];
    g_tvec[c] = s;
}

// ---------------------------------------------------------------------------
// Elementwise reducers (float4), N = E_DIM layouts only.
// mode 0: fusion  (+tvec)      -> g_f
// mode 1: sigmoid               -> g_gate
// mode 2: residual (+g_f)       -> g_ff
// mode 3: residual (+g_ff)      -> g_ff
// ---------------------------------------------------------------------------
__global__ void reduce_elem(const float* __restrict__ bias, int ksp, int mode) {
    int q = blockIdx.x * 256 + threadIdx.x;       // float4 index, 32*E/4 = 32768
    int e = q * 4;
    int c = e & (E_DIM - 1);
    float4 v = *reinterpret_cast<const float4*>(&bias[c]);
    const float4* p4 = reinterpret_cast<const float4*>(g_part);
    for (int sl = 0; sl < ksp; ++sl) {
        float4 t = p4[(size_t)sl * (MROWS * E_DIM / 4) + q];
        v.x += t.x; v.y += t.y; v.z += t.z; v.w += t.w;
    }
    if (mode == 0) {
        float4 t = *reinterpret_cast<const float4*>(&g_tvec[c]);
        v.x += t.x; v.y += t.y; v.z += t.z; v.w += t.w;
        *reinterpret_cast<float4*>(&g_f[e]) = v;
    } else if (mode == 1) {
        v.x = 1.f / (1.f + expf(-v.x));
        v.y = 1.f / (1.f + expf(-v.y));
        v.z = 1.f / (1.f + expf(-v.z));
        v.w = 1.f / (1.f + expf(-v.w));
        *reinterpret_cast<float4*>(&g_gate[e]) = v;
    } else {
        const float* resid = (mode == 2) ? g_f : g_ff;
        float4 t = *reinterpret_cast<const float4*>(&resid[e]);
        v.x += t.x; v.y += t.y; v.z += t.z; v.w += t.w;
        *reinterpret_cast<float4*>(&g_ff[e]) = v;
    }
}

// ---------------------------------------------------------------------------
// Fused split-K reduce + BN + ReLU. Block = 256 threads, 32 columns.
// thread (c = t&31, mg = t>>5) sums 4 rows x ksp slices (coalesced), smem
// holds the 32x32 tile, per-column stats, normalized write.
// outSel: 0 -> g_r1 (N=E), 1 -> g_h (N=H)
// ---------------------------------------------------------------------------
__global__ void reduce_bn_relu(const float* __restrict__ bias,
                               const float* __restrict__ gam,
                               const float* __restrict__ bet,
                               int N, int ksp, int outSel) {
    __shared__ float ssum[MROWS][33];
    __shared__ float smu[MROWS], srs[MROWS];
    int c  = threadIdx.x & 31;
    int mg = threadIdx.x >> 5;
    int gc = blockIdx.x * 32 + c;
    float b = bias[gc];
#pragma unroll
    for (int r = 0; r < 4; ++r) {
        int m = mg * 4 + r;
        float s = b;
        const float* p = g_part + (size_t)m * N + gc;
#pragma unroll 8
        for (int sl = 0; sl < ksp; ++sl)
            s += p[(size_t)sl * MROWS * N];
        ssum[m][c] = s;
    }
    __syncthreads();
    if (threadIdx.x < 32) {
        int cc = threadIdx.x;
        float su = 0.f;
#pragma unroll
        for (int m = 0; m < MROWS; ++m) su += ssum[m][cc];
        float mu = su * (1.f / 32.f);
        float s2 = 0.f;
#pragma unroll
        for (int m = 0; m < MROWS; ++m) { float d = ssum[m][cc] - mu; s2 += d * d; }
        smu[cc] = mu;
        srs[cc] = rsqrtf(s2 * (1.f / 32.f) + 1e-5f);
    }
    __syncthreads();
    float gg = gam[gc], bb = bet[gc];
    float* out = outSel ? g_h : g_r1;
#pragma unroll
    for (int r = 0; r < 4; ++r) {
        int m = mg * 4 + r;
        float o = (ssum[m][c] - smu[c]) * srs[c] * gg + bb;
        out[(size_t)m * N + gc] = fmaxf(o, 0.f);
    }
}

// ---------------------------------------------------------------------------
// final: R = img*g + ff*(1-g); broadcast 32x along the text axis (float4)
// ---------------------------------------------------------------------------
__global__ void final_kernel(const float* __restrict__ img, float* __restrict__ out) {
    int q = blockIdx.x * 256 + threadIdx.x;   // 32768 float4 groups
    float4 gv = *reinterpret_cast<const float4*>(&g_gate[q * 4]);
    float4 fv = *reinterpret_cast<const float4*>(&g_ff[q * 4]);
    float4 iv = *reinterpret_cast<const float4*>(&img[q * 4]);
    float4 r;
    r.x = iv.x * gv.x + fv.x * (1.f - gv.x);
    r.y = iv.y * gv.y + fv.y * (1.f - gv.y);
    r.z = iv.z * gv.z + fv.z * (1.f - gv.z);
    r.w = iv.w * gv.w + fv.w * (1.f - gv.w);
    float4* o4 = reinterpret_cast<float4*>(out);
#pragma unroll
    for (int j = 0; j < 32; ++j)
        o4[(size_t)j * 32768 + q] = r;
}

// ---------------------------------------------------------------------------
extern "C" void kernel_launch(void* const* d_in, const int* in_sizes, int n_in,
                              void* d_out, int out_size) {
    const float* img     = (const float*)d_in[0];
    // d_in[1] = text_features: provably unused (BN of broadcast row == bias)
    const float* fs_bn_g = (const float*)d_in[2];
    const float* fs_bn_b = (const float*)d_in[3];
    const float* fs_w    = (const float*)d_in[4];
    const float* fs_b    = (const float*)d_in[5];
    const float* gt_w1   = (const float*)d_in[6];
    const float* gt_b1   = (const float*)d_in[7];
    const float* gt_bn_g = (const float*)d_in[8];
    const float* gt_bn_b = (const float*)d_in[9];
    const float* gt_w2   = (const float*)d_in[10];
    const float* gt_b2   = (const float*)d_in[11];
    const float* ee_w1   = (const float*)d_in[12];
    const float* ee_b1   = (const float*)d_in[13];
    const float* ee_bn_g = (const float*)d_in[14];
    const float* ee_bn_b = (const float*)d_in[15];
    const float* ee_w2   = (const float*)d_in[16];
    const float* ee_b2   = (const float*)d_in[17];
    float* out = (float*)d_out;

    // 0) image BN + relu, constant text vector
    pre_kernel<<<16, 256>>>(img, fs_bn_g, fs_bn_b);

    // 1) fusion: f = xi @ fs_w[0:E] + tvec + fs_b
    gemv_kernel<<<dim3(16, 32), 256>>>(fs_w + (size_t)E_DIM * E_DIM, 128);
    reduce_tvec<<<16, 256>>>();
    gemm_kernel<<<dim3(16, 32), 128>>>(SEL_XI, fs_w, E_DIM, E_DIM, 128);
    reduce_elem<<<128, 256>>>(fs_b, 32, 0);

    // 2) gating
    gemm_kernel<<<dim3(16, 32), 128>>>(SEL_F, gt_w1, E_DIM, E_DIM, 128);
    reduce_bn_relu<<<128, 256>>>(gt_b1, gt_bn_g, gt_bn_b, E_DIM, 32, 0);
    gemm_kernel<<<dim3(16, 32), 128>>>(SEL_R1, gt_w2, E_DIM, E_DIM, 128);
    reduce_elem<<<128, 256>>>(gt_b2, 32, 1);

    // 3) three error-encoding residual blocks
    for (int i = 0; i < 3; ++i) {
        gemm_kernel<<<dim3(8, 64), 128>>>((i == 0) ? SEL_F : SEL_FF,
                                          ee_w1 + (size_t)i * E_DIM * H_DIM,
                                          E_DIM, H_DIM, 64);
        reduce_bn_relu<<<64, 256>>>(ee_b1 + i * H_DIM, ee_bn_g + i * H_DIM,
                                    ee_bn_b + i * H_DIM, H_DIM, 64, 1);
        gemm_kernel<<<dim3(16, 32), 128>>>(SEL_H, ee_w2 + (size_t)i * H_DIM * E_DIM,
                                           H_DIM, E_DIM, 64);
        reduce_elem<<<128, 256>>>(ee_b2 + i * E_DIM, 32, (i == 0) ? 2 : 3);
    }

    // 4) gate-combine and broadcast to [32, 32, 4096]
    final_kernel<<<128, 256>>>(img, out);

    (void)in_sizes; (void)n_in; (void)out_size;
}